// round 14
// baseline (speedup 1.0000x reference)
#include <cuda_runtime.h>
#include <cuda_fp16.h>
#include <cstdint>

#define BATCH 8
#define CIN   64
#define COUT  64
#define HH    112
#define WW    112
#define HWSZ  (HH*WW)

// ---------------- precomputed fp16 planes ----------------
__device__ __align__(128) __half g_x_h[BATCH * HH * WW * CIN];   // [b][y][x][c]
__device__ __align__(128) __half g_w_h[9 * COUT * CIN];          // [t][o][c]

// ================= per-batch prep: x transpose+convert (+ w reorder in b==0) =================
// grid.x = 224 (+64 w-CTAs when b==0), 128 threads.
#define PS 114   // EVEN stride in halves -> all __half2 STS 4B-aligned

__global__ __launch_bounds__(128, 15)
void prep_kernel(const float* __restrict__ x, const float* __restrict__ w, int b)
{
    __shared__ __align__(16) __half stile[CIN * PS];
    const int tid = threadIdx.x;
    const int bx  = blockIdx.x;

    if (bx >= 224) {
        // ---- w-prep (only present in the b==0 launch): 64 CTAs x 576 elements ----
        const int slot = bx - 224;                // 0..63
        #pragma unroll
        for (int j = 0; j < 5; j++) {
            int el = j * 128 + tid;
            if (el < 576) {
                int e = slot * 576 + el;          // 0..36863
                int c = e & 63, o = (e >> 6) & 63, t = e >> 12;
                g_w_h[(t * COUT + o) * CIN + c] =
                    __float2half(w[o * (CIN * 9) + c * 9 + t]);
            }
        }
        return;
    }

    // ---- x-prep: one (y, x-half) slice of 56 positions for batch b ----
    const int y    = bx >> 1;
    const int half = (bx & 1) * 56;
    const float* xb = x + ((size_t)b * CIN) * HWSZ + y * WW + half;

    #pragma unroll
    for (int k = 0; k < 8; k++) {
        int u   = k * 128 + tid;
        int c   = u >> 4;
        int sub = u & 15;
        if (sub < 14) {
            float4 v = *(const float4*)&xb[(size_t)c * HWSZ + sub * 4];
            __half2 h0 = __floats2half2_rn(v.x, v.y);
            __half2 h1 = __floats2half2_rn(v.z, v.w);
            *(__half2*)&stile[c * PS + sub * 4]     = h0;
            *(__half2*)&stile[c * PS + sub * 4 + 2] = h1;
        }
    }
    __syncthreads();

    const int cg = tid & 7;
    #pragma unroll
    for (int j = 0; j < 4; j++) {
        int xx = j * 16 + (tid >> 3);
        if (xx < 56) {
            __half h[8];
            #pragma unroll
            for (int k = 0; k < 8; k++)
                h[k] = stile[(cg * 8 + k) * PS + xx];
            *(uint4*)&g_x_h[((size_t)((b * HH + y) * WW) + half + xx) * CIN + cg * 8] =
                *(uint4*)h;
        }
    }
}

// ================= base-ISA async/MMA primitives =================
__device__ __forceinline__ uint32_t smem_u32(const void* p) {
    uint32_t a;
    asm("{ .reg .u64 t; cvta.to.shared.u64 t, %1; cvt.u32.u64 %0, t; }" : "=r"(a) : "l"(p));
    return a;
}
__device__ __forceinline__ void cp16(uint32_t dst, const void* src, uint32_t sz) {
    asm volatile("cp.async.cg.shared.global [%0], [%1], 16, %2;"
                 :: "r"(dst), "l"(src), "r"(sz) : "memory");
}
#define CP_COMMIT() asm volatile("cp.async.commit_group;" ::: "memory")
#define CP_WAIT0()  asm volatile("cp.async.wait_group 0;" ::: "memory")

__device__ __forceinline__ void ldmx4(uint32_t* r, uint32_t addr) {
    asm volatile("ldmatrix.sync.aligned.m8n8.x4.shared.b16 {%0,%1,%2,%3}, [%4];"
                 : "=r"(r[0]), "=r"(r[1]), "=r"(r[2]), "=r"(r[3]) : "r"(addr));
}
__device__ __forceinline__ void mma16816(float* c, const uint32_t* a,
                                         uint32_t b0, uint32_t b1) {
    asm volatile("mma.sync.aligned.m16n8k16.row.col.f32.f16.f16.f32 "
                 "{%0,%1,%2,%3}, {%4,%5,%6,%7}, {%8,%9}, {%0,%1,%2,%3};"
                 : "+f"(c[0]), "+f"(c[1]), "+f"(c[2]), "+f"(c[3])
                 : "r"(a[0]), "r"(a[1]), "r"(a[2]), "r"(a[3]), "r"(b0), "r"(b1));
}

// ================= main kernel: M=64 tiles, per-batch grid (196) =================
#define X_OFF   0
#define Z_OFF   12800
#define B_OFF   12928
#define B_BUF   8192
#define SMEM_SZ 29312
#define NT      128

__global__ __launch_bounds__(NT, 5)
void rconv_mma_kernel(const int* __restrict__ mask, float* __restrict__ out, int b)
{
    extern __shared__ __align__(128) char smem[];
    const uint32_t sb = smem_u32(smem);

    const int tid  = threadIdx.x;
    const int wid  = tid >> 5;
    const int lane = tid & 31;
    const int tile = blockIdx.x;            // 0..195
    const int x0   = (tile % 14) * 8;
    const int y0   = (tile / 14) * 8;

    const int wm = wid & 1;
    const int wn = wid >> 1;
    const int m0 = wm * 32;
    const int n0 = wn * 32;

    if (tid < 32) ((float*)(smem + Z_OFF))[tid] = 0.0f;

    // ---- per-thread ldmatrix geometry ----
    const int ch      = lane >> 4;
    const int lanerow = lane & 15;
    int  rb[2], mk[2];
    #pragma unroll
    for (int mi = 0; mi < 2; mi++) {
        int p  = m0 + mi * 16 + lanerow;
        int py = p >> 3, px = p & 7;
        rb[mi] = py * 10 + px;
        mk[mi] = __ldg(&mask[(y0 + py) * WW + (x0 + px)]);
    }
    const int nlocal = (lane & 7) + ((lane >> 4) << 3);
    const int khalf  = (lane >> 3) & 1;
    int boff[2], bsw[2];
    #pragma unroll
    for (int ntp = 0; ntp < 2; ntp++) {
        int orow = n0 + ntp * 16 + nlocal;
        boff[ntp] = orow * 128;
        bsw[ntp]  = orow & 7;
    }
    const uint32_t zaddr = sb + Z_OFF;

    // ---- prologue: stage x tile (10x10 rows) + B[0] ----
    for (int i = tid; i < 800; i += NT) {
        int r  = i >> 3;
        int j  = i & 7;
        int iy = r / 10, ix = r - iy * 10;
        int gy = y0 - 1 + iy, gx = x0 - 1 + ix;
        bool ok = (gy >= 0 && gy < HH && gx >= 0 && gx < WW);
        const __half* src = g_x_h +
            (ok ? (((size_t)((b * HH + gy) * WW + gx)) * CIN + j * 8) : 0);
        uint32_t dst = sb + X_OFF + r * 128 + ((j ^ (r & 7)) << 4);
        cp16(dst, src, ok ? 16u : 0u);
    }
    #pragma unroll
    for (int k = 0; k < 4; k++) {
        int i = k * NT + tid;
        int o = i >> 3, j = i & 7;
        const __half* src = g_w_h + ((0 * COUT + o) * CIN + j * 8);
        uint32_t dst = sb + B_OFF + o * 128 + ((j ^ (o & 7)) << 4);
        cp16(dst, src, 16u);
    }
    CP_COMMIT();

    float C[2][4][4];
    #pragma unroll
    for (int mi = 0; mi < 2; mi++)
        #pragma unroll
        for (int nt = 0; nt < 4; nt++)
            #pragma unroll
            for (int k = 0; k < 4; k++) C[mi][nt][k] = 0.0f;

    int buf = 0;
    #pragma unroll 1
    for (int t = 0; t < 9; t++) {
        CP_WAIT0();
        __syncthreads();

        if (t < 8) {
            #pragma unroll
            for (int k = 0; k < 4; k++) {
                int i = k * NT + tid;
                int o = i >> 3, j = i & 7;
                const __half* src = g_w_h + (((t + 1) * COUT + o) * CIN + j * 8);
                uint32_t dst = sb + B_OFF + (buf ^ 1) * B_BUF + o * 128 + ((j ^ (o & 7)) << 4);
                cp16(dst, src, 16u);
            }
            CP_COMMIT();
        }

        const int kh   = t / 3;
        const int toff = t + kh * 7;         // kh*10 + kw
        int  r128[2], rm[2];
        bool msk[2];
        #pragma unroll
        for (int mi = 0; mi < 2; mi++) {
            int r = rb[mi] + toff;
            r128[mi] = r << 7;
            rm[mi]   = r & 7;
            msk[mi]  = (mk[mi] == t);
        }
        const uint32_t bb = sb + B_OFF + buf * B_BUF;

        #pragma unroll
        for (int kc = 0; kc < 4; kc++) {
            uint32_t A[2][4], Bv[2][4];
            #pragma unroll
            for (int mi = 0; mi < 2; mi++) {
                uint32_t sw = (uint32_t)((((kc << 1) | ch) ^ rm[mi]) << 4);
                uint32_t ah = msk[mi] ? zaddr : (sb + X_OFF + r128[mi] + sw);
                ldmx4(A[mi], ah);
            }
            #pragma unroll
            for (int ntp = 0; ntp < 2; ntp++) {
                uint32_t sw = (uint32_t)((((kc << 1) | khalf) ^ bsw[ntp]) << 4);
                ldmx4(Bv[ntp], bb + boff[ntp] + sw);
            }
            #pragma unroll
            for (int mi = 0; mi < 2; mi++)
                #pragma unroll
                for (int ntp = 0; ntp < 2; ntp++)
                    #pragma unroll
                    for (int s = 0; s < 2; s++)
                        mma16816(C[mi][ntp * 2 + s], A[mi],
                                 Bv[ntp][2 * s], Bv[ntp][2 * s + 1]);
        }
        buf ^= 1;
    }

    // ---- epilogue ----
    __syncthreads();
    float* sC = (float*)smem;
    const int g   = lane >> 2;
    const int tg2 = (lane & 3) * 2;
    #pragma unroll
    for (int mi = 0; mi < 2; mi++)
        #pragma unroll
        for (int nt = 0; nt < 4; nt++) {
            int mrow = m0 + mi * 16 + g;
            int col  = n0 + nt * 8 + tg2;
            *(float2*)(sC + mrow * 66 + col)       = make_float2(C[mi][nt][0], C[mi][nt][1]);
            *(float2*)(sC + (mrow + 8) * 66 + col) = make_float2(C[mi][nt][2], C[mi][nt][3]);
        }
    __syncthreads();

    #pragma unroll
    for (int it = 0; it < 8; it++) {
        int idx = it * NT + tid;
        int o   = idx >> 4;
        int rem = idx & 15;
        int py  = rem >> 1;
        int px  = (rem & 1) * 4;
        int mb  = py * 8 + px;
        float4 v;
        v.x = sC[(mb + 0) * 66 + o];
        v.y = sC[(mb + 1) * 66 + o];
        v.z = sC[(mb + 2) * 66 + o];
        v.w = sC[(mb + 3) * 66 + o];
        *(float4*)(out + ((size_t)(b * COUT + o)) * HWSZ + (y0 + py) * WW + (x0 + px)) = v;
    }
}

// ================= launch: two-stream overlapped pipeline =================
// preps sequential on the default (captured) stream; main(b) on a forked
// stream gated by event e_b; join back via event. No device memory is
// allocated. Stream/events are intentionally NOT destroyed: kernel_launch
// runs only for correctness + capture (~2-3 calls), and destroying objects
// referenced by an in-progress capture is the riskier operation.
extern "C" void kernel_launch(void* const* d_in, const int* in_sizes, int n_in,
                              void* d_out, int out_size)
{
    (void)in_sizes; (void)n_in; (void)out_size;
    const float* x    = (const float*)d_in[0];
    const float* w    = (const float*)d_in[1];
    const int*   mask = (const int*)d_in[2];
    float*       out  = (float*)d_out;

    cudaFuncSetAttribute(rconv_mma_kernel,
                         cudaFuncAttributeMaxDynamicSharedMemorySize, SMEM_SZ);

    cudaStream_t s2;
    cudaStreamCreateWithFlags(&s2, cudaStreamNonBlocking);
    cudaEvent_t ev[BATCH], em;
    for (int b = 0; b < BATCH; b++)
        cudaEventCreateWithFlags(&ev[b], cudaEventDisableTiming);
    cudaEventCreateWithFlags(&em, cudaEventDisableTiming);

    // preps on default stream; batch 0 carries the 64 w-prep CTAs
    for (int b = 0; b < BATCH; b++) {
        prep_kernel<<<(b == 0 ? 288 : 224), 128, 0, 0>>>(x, w, b);
        cudaEventRecord(ev[b], 0);
    }
    // mains on forked stream, each gated on its batch's prep
    for (int b = 0; b < BATCH; b++) {
        cudaStreamWaitEvent(s2, ev[b], 0);
        rconv_mma_kernel<<<196, NT, SMEM_SZ, s2>>>(mask, out, b);
    }
    // join back to the default stream
    cudaEventRecord(em, s2);
    cudaStreamWaitEvent(0, em, 0);
}

// round 15
// speedup vs baseline: 1.6175x; 1.6175x over previous
#include <cuda_runtime.h>
#include <cuda_fp16.h>
#include <cstdint>

#define BATCH 8
#define CIN   64
#define COUT  64
#define HH    112
#define WW    112
#define HWSZ  (HH*WW)

// ---------------- precomputed fp16 planes ----------------
__device__ __align__(128) __half g_x_h[BATCH * HH * WW * CIN];   // [b][y][x][c]
__device__ __align__(128) __half g_w_h[9 * COUT * CIN];          // [t][o][c]

// ================= prep: 4 batches per launch (grid 224|288 x 4) =================
#define PS 114   // EVEN stride in halves -> all __half2 STS 4B-aligned

__global__ __launch_bounds__(128, 15)
void prep_kernel(const float* __restrict__ x, const float* __restrict__ w, int bbase)
{
    __shared__ __align__(16) __half stile[CIN * PS];
    const int tid = threadIdx.x;
    const int bx  = blockIdx.x;
    const int b   = bbase + blockIdx.y;

    if (bx >= 224) {
        // w-prep CTAs exist only in the first launch's y==0 row
        if (blockIdx.y != 0) return;
        const int slot = bx - 224;                // 0..63
        #pragma unroll
        for (int j = 0; j < 5; j++) {
            int el = j * 128 + tid;
            if (el < 576) {
                int e = slot * 576 + el;          // 0..36863
                int c = e & 63, o = (e >> 6) & 63, t = e >> 12;
                g_w_h[(t * COUT + o) * CIN + c] =
                    __float2half(w[o * (CIN * 9) + c * 9 + t]);
            }
        }
        return;
    }

    const int y    = bx >> 1;
    const int half = (bx & 1) * 56;
    const float* xb = x + ((size_t)b * CIN) * HWSZ + y * WW + half;

    #pragma unroll
    for (int k = 0; k < 8; k++) {
        int u   = k * 128 + tid;
        int c   = u >> 4;
        int sub = u & 15;
        if (sub < 14) {
            float4 v = *(const float4*)&xb[(size_t)c * HWSZ + sub * 4];
            __half2 h0 = __floats2half2_rn(v.x, v.y);
            __half2 h1 = __floats2half2_rn(v.z, v.w);
            *(__half2*)&stile[c * PS + sub * 4]     = h0;
            *(__half2*)&stile[c * PS + sub * 4 + 2] = h1;
        }
    }
    __syncthreads();

    const int cg = tid & 7;
    #pragma unroll
    for (int j = 0; j < 4; j++) {
        int xx = j * 16 + (tid >> 3);
        if (xx < 56) {
            __half h[8];
            #pragma unroll
            for (int k = 0; k < 8; k++)
                h[k] = stile[(cg * 8 + k) * PS + xx];
            *(uint4*)&g_x_h[((size_t)((b * HH + y) * WW) + half + xx) * CIN + cg * 8] =
                *(uint4*)h;
        }
    }
}

// ================= base-ISA async/MMA primitives =================
__device__ __forceinline__ uint32_t smem_u32(const void* p) {
    uint32_t a;
    asm("{ .reg .u64 t; cvta.to.shared.u64 t, %1; cvt.u32.u64 %0, t; }" : "=r"(a) : "l"(p));
    return a;
}
__device__ __forceinline__ void cp16(uint32_t dst, const void* src, uint32_t sz) {
    asm volatile("cp.async.cg.shared.global [%0], [%1], 16, %2;"
                 :: "r"(dst), "l"(src), "r"(sz) : "memory");
}
#define CP_COMMIT() asm volatile("cp.async.commit_group;" ::: "memory")
#define CP_WAIT0()  asm volatile("cp.async.wait_group 0;" ::: "memory")

__device__ __forceinline__ void ldmx4(uint32_t* r, uint32_t addr) {
    asm volatile("ldmatrix.sync.aligned.m8n8.x4.shared.b16 {%0,%1,%2,%3}, [%4];"
                 : "=r"(r[0]), "=r"(r[1]), "=r"(r[2]), "=r"(r[3]) : "r"(addr));
}
__device__ __forceinline__ void mma16816(float* c, const uint32_t* a,
                                         uint32_t b0, uint32_t b1) {
    asm volatile("mma.sync.aligned.m16n8k16.row.col.f32.f16.f16.f32 "
                 "{%0,%1,%2,%3}, {%4,%5,%6,%7}, {%8,%9}, {%0,%1,%2,%3};"
                 : "+f"(c[0]), "+f"(c[1]), "+f"(c[2]), "+f"(c[3])
                 : "r"(a[0]), "r"(a[1]), "r"(a[2]), "r"(a[3]), "r"(b0), "r"(b1));
}

// ================= main kernel: M=64 tiles, 4 batches per launch =================
#define X_OFF   0
#define Z_OFF   12800
#define B_OFF   12928
#define B_BUF   8192
#define SMEM_SZ 29312
#define NT      128

__global__ __launch_bounds__(NT, 5)
void rconv_mma_kernel(const int* __restrict__ mask, float* __restrict__ out, int bbase)
{
    extern __shared__ __align__(128) char smem[];
    const uint32_t sb = smem_u32(smem);

    const int tid  = threadIdx.x;
    const int wid  = tid >> 5;
    const int lane = tid & 31;
    const int tile = blockIdx.x;            // 0..195
    const int b    = bbase + blockIdx.y;
    const int x0   = (tile % 14) * 8;
    const int y0   = (tile / 14) * 8;

    const int wm = wid & 1;
    const int wn = wid >> 1;
    const int m0 = wm * 32;
    const int n0 = wn * 32;

    if (tid < 32) ((float*)(smem + Z_OFF))[tid] = 0.0f;

    // ---- per-thread ldmatrix geometry ----
    const int ch      = lane >> 4;
    const int lanerow = lane & 15;
    int  rb[2], mk[2];
    #pragma unroll
    for (int mi = 0; mi < 2; mi++) {
        int p  = m0 + mi * 16 + lanerow;
        int py = p >> 3, px = p & 7;
        rb[mi] = py * 10 + px;
        mk[mi] = __ldg(&mask[(y0 + py) * WW + (x0 + px)]);
    }
    const int nlocal = (lane & 7) + ((lane >> 4) << 3);
    const int khalf  = (lane >> 3) & 1;
    int boff[2], bsw[2];
    #pragma unroll
    for (int ntp = 0; ntp < 2; ntp++) {
        int orow = n0 + ntp * 16 + nlocal;
        boff[ntp] = orow * 128;
        bsw[ntp]  = orow & 7;
    }
    const uint32_t zaddr = sb + Z_OFF;

    // ---- prologue: stage x tile (10x10 rows) + B[0] ----
    for (int i = tid; i < 800; i += NT) {
        int r  = i >> 3;
        int j  = i & 7;
        int iy = r / 10, ix = r - iy * 10;
        int gy = y0 - 1 + iy, gx = x0 - 1 + ix;
        bool ok = (gy >= 0 && gy < HH && gx >= 0 && gx < WW);
        const __half* src = g_x_h +
            (ok ? (((size_t)((b * HH + gy) * WW + gx)) * CIN + j * 8) : 0);
        uint32_t dst = sb + X_OFF + r * 128 + ((j ^ (r & 7)) << 4);
        cp16(dst, src, ok ? 16u : 0u);
    }
    #pragma unroll
    for (int k = 0; k < 4; k++) {
        int i = k * NT + tid;
        int o = i >> 3, j = i & 7;
        const __half* src = g_w_h + ((0 * COUT + o) * CIN + j * 8);
        uint32_t dst = sb + B_OFF + o * 128 + ((j ^ (o & 7)) << 4);
        cp16(dst, src, 16u);
    }
    CP_COMMIT();

    float C[2][4][4];
    #pragma unroll
    for (int mi = 0; mi < 2; mi++)
        #pragma unroll
        for (int nt = 0; nt < 4; nt++)
            #pragma unroll
            for (int k = 0; k < 4; k++) C[mi][nt][k] = 0.0f;

    int buf = 0;
    #pragma unroll 1
    for (int t = 0; t < 9; t++) {
        CP_WAIT0();
        __syncthreads();

        if (t < 8) {
            #pragma unroll
            for (int k = 0; k < 4; k++) {
                int i = k * NT + tid;
                int o = i >> 3, j = i & 7;
                const __half* src = g_w_h + (((t + 1) * COUT + o) * CIN + j * 8);
                uint32_t dst = sb + B_OFF + (buf ^ 1) * B_BUF + o * 128 + ((j ^ (o & 7)) << 4);
                cp16(dst, src, 16u);
            }
            CP_COMMIT();
        }

        const int kh   = t / 3;
        const int toff = t + kh * 7;         // kh*10 + kw
        int  r128[2], rm[2];
        bool msk[2];
        #pragma unroll
        for (int mi = 0; mi < 2; mi++) {
            int r = rb[mi] + toff;
            r128[mi] = r << 7;
            rm[mi]   = r & 7;
            msk[mi]  = (mk[mi] == t);
        }
        const uint32_t bb = sb + B_OFF + buf * B_BUF;

        #pragma unroll
        for (int kc = 0; kc < 4; kc++) {
            uint32_t A[2][4], Bv[2][4];
            #pragma unroll
            for (int mi = 0; mi < 2; mi++) {
                uint32_t sw = (uint32_t)((((kc << 1) | ch) ^ rm[mi]) << 4);
                uint32_t ah = msk[mi] ? zaddr : (sb + X_OFF + r128[mi] + sw);
                ldmx4(A[mi], ah);
            }
            #pragma unroll
            for (int ntp = 0; ntp < 2; ntp++) {
                uint32_t sw = (uint32_t)((((kc << 1) | khalf) ^ bsw[ntp]) << 4);
                ldmx4(Bv[ntp], bb + boff[ntp] + sw);
            }
            #pragma unroll
            for (int mi = 0; mi < 2; mi++)
                #pragma unroll
                for (int ntp = 0; ntp < 2; ntp++)
                    #pragma unroll
                    for (int s = 0; s < 2; s++)
                        mma16816(C[mi][ntp * 2 + s], A[mi],
                                 Bv[ntp][2 * s], Bv[ntp][2 * s + 1]);
        }
        buf ^= 1;
    }

    // ---- epilogue ----
    __syncthreads();
    float* sC = (float*)smem;
    const int g   = lane >> 2;
    const int tg2 = (lane & 3) * 2;
    #pragma unroll
    for (int mi = 0; mi < 2; mi++)
        #pragma unroll
        for (int nt = 0; nt < 4; nt++) {
            int mrow = m0 + mi * 16 + g;
            int col  = n0 + nt * 8 + tg2;
            *(float2*)(sC + mrow * 66 + col)       = make_float2(C[mi][nt][0], C[mi][nt][1]);
            *(float2*)(sC + (mrow + 8) * 66 + col) = make_float2(C[mi][nt][2], C[mi][nt][3]);
        }
    __syncthreads();

    #pragma unroll
    for (int it = 0; it < 8; it++) {
        int idx = it * NT + tid;
        int o   = idx >> 4;
        int rem = idx & 15;
        int py  = rem >> 1;
        int px  = (rem & 1) * 4;
        int mb  = py * 8 + px;
        float4 v;
        v.x = sC[(mb + 0) * 66 + o];
        v.y = sC[(mb + 1) * 66 + o];
        v.z = sC[(mb + 2) * 66 + o];
        v.w = sC[(mb + 3) * 66 + o];
        *(float4*)(out + ((size_t)(b * COUT + o)) * HWSZ + (y0 + py) * WW + (x0 + px)) = v;
    }
}

// ================= launch: 2-stage coarse pipeline =================
// prepA (b0-3 + w, 1216 CTAs) -> eA -> mainA (784 CTAs) on s2
// prepB (b4-7, 896 CTAs)      -> eB -> mainB (784 CTAs) on s3
// prepB and mainB overlap mainA; join both streams back to origin.
extern "C" void kernel_launch(void* const* d_in, const int* in_sizes, int n_in,
                              void* d_out, int out_size)
{
    (void)in_sizes; (void)n_in; (void)out_size;
    const float* x    = (const float*)d_in[0];
    const float* w    = (const float*)d_in[1];
    const int*   mask = (const int*)d_in[2];
    float*       out  = (float*)d_out;

    cudaFuncSetAttribute(rconv_mma_kernel,
                         cudaFuncAttributeMaxDynamicSharedMemorySize, SMEM_SZ);

    static cudaStream_t s2 = nullptr, s3 = nullptr;
    static cudaEvent_t eA = nullptr, eB = nullptr, e2 = nullptr, e3 = nullptr;
    if (!s2) {
        cudaStreamCreateWithFlags(&s2, cudaStreamNonBlocking);
        cudaStreamCreateWithFlags(&s3, cudaStreamNonBlocking);
        cudaEventCreateWithFlags(&eA, cudaEventDisableTiming);
        cudaEventCreateWithFlags(&eB, cudaEventDisableTiming);
        cudaEventCreateWithFlags(&e2, cudaEventDisableTiming);
        cudaEventCreateWithFlags(&e3, cudaEventDisableTiming);
    }

    prep_kernel<<<dim3(288, 4), 128, 0, 0>>>(x, w, 0);   // b0-3 + w-prep
    cudaEventRecord(eA, 0);
    prep_kernel<<<dim3(224, 4), 128, 0, 0>>>(x, w, 4);   // b4-7
    cudaEventRecord(eB, 0);

    cudaStreamWaitEvent(s2, eA, 0);
    rconv_mma_kernel<<<dim3(196, 4), NT, SMEM_SZ, s2>>>(mask, out, 0);
    cudaStreamWaitEvent(s3, eB, 0);
    rconv_mma_kernel<<<dim3(196, 4), NT, SMEM_SZ, s3>>>(mask, out, 4);

    cudaEventRecord(e2, s2);
    cudaEventRecord(e3, s3);
    cudaStreamWaitEvent(0, e2, 0);
    cudaStreamWaitEvent(0, e3, 0);
}

// round 16
// speedup vs baseline: 1.6311x; 1.0084x over previous
#include <cuda_runtime.h>
#include <cuda_fp16.h>
#include <cstdint>

#define BATCH 8
#define CIN   64
#define COUT  64
#define HH    112
#define WW    112
#define HWSZ  (HH*WW)

// ---------------- precomputed fp16 planes ----------------
__device__ __align__(128) __half g_x_h[BATCH * HH * WW * CIN];   // [b][y][x][c]
__device__ __align__(128) __half g_w_h[9 * COUT * CIN];          // [t][o][c]

// ================= fused prep (R12 known-good): all batches, one launch =================
#define PS 114   // EVEN stride in halves -> all __half2 STS 4B-aligned

__global__ __launch_bounds__(128, 15)
void prep_kernel(const float* __restrict__ x, const float* __restrict__ w)
{
    __shared__ __align__(16) __half stile[CIN * PS];
    const int tid = threadIdx.x;
    const int bx  = blockIdx.x;
    const int b   = blockIdx.y;

    if (bx >= 224) {
        // ---- w-prep: 8 slots x 8 batch-rows = 64 slices x 576 elements ----
        const int slot = (bx - 224) + 8 * b;      // 0..63
        #pragma unroll
        for (int j = 0; j < 5; j++) {
            int el = j * 128 + tid;
            if (el < 576) {
                int e = slot * 576 + el;          // 0..36863
                int c = e & 63, o = (e >> 6) & 63, t = e >> 12;
                g_w_h[(t * COUT + o) * CIN + c] =
                    __float2half(w[o * (CIN * 9) + c * 9 + t]);
            }
        }
        return;
    }

    const int y    = bx >> 1;
    const int half = (bx & 1) * 56;
    const float* xb = x + ((size_t)b * CIN) * HWSZ + y * WW + half;

    #pragma unroll
    for (int k = 0; k < 8; k++) {
        int u   = k * 128 + tid;
        int c   = u >> 4;
        int sub = u & 15;
        if (sub < 14) {
            float4 v = *(const float4*)&xb[(size_t)c * HWSZ + sub * 4];
            __half2 h0 = __floats2half2_rn(v.x, v.y);
            __half2 h1 = __floats2half2_rn(v.z, v.w);
            *(__half2*)&stile[c * PS + sub * 4]     = h0;
            *(__half2*)&stile[c * PS + sub * 4 + 2] = h1;
        }
    }
    __syncthreads();

    const int cg = tid & 7;
    #pragma unroll
    for (int j = 0; j < 4; j++) {
        int xx = j * 16 + (tid >> 3);
        if (xx < 56) {
            __half h[8];
            #pragma unroll
            for (int k = 0; k < 8; k++)
                h[k] = stile[(cg * 8 + k) * PS + xx];
            *(uint4*)&g_x_h[((size_t)((b * HH + y) * WW) + half + xx) * CIN + cg * 8] =
                *(uint4*)h;
        }
    }
}

// ================= base-ISA async/MMA primitives =================
__device__ __forceinline__ uint32_t smem_u32(const void* p) {
    uint32_t a;
    asm("{ .reg .u64 t; cvta.to.shared.u64 t, %1; cvt.u32.u64 %0, t; }" : "=r"(a) : "l"(p));
    return a;
}
__device__ __forceinline__ void cp16(uint32_t dst, const void* src, uint32_t sz) {
    asm volatile("cp.async.cg.shared.global [%0], [%1], 16, %2;"
                 :: "r"(dst), "l"(src), "r"(sz) : "memory");
}
#define CP_COMMIT() asm volatile("cp.async.commit_group;" ::: "memory")
#define CP_WAIT0()  asm volatile("cp.async.wait_group 0;" ::: "memory")

__device__ __forceinline__ void ldmx4(uint32_t* r, uint32_t addr) {
    asm volatile("ldmatrix.sync.aligned.m8n8.x4.shared.b16 {%0,%1,%2,%3}, [%4];"
                 : "=r"(r[0]), "=r"(r[1]), "=r"(r[2]), "=r"(r[3]) : "r"(addr));
}
__device__ __forceinline__ void mma16816(float* c, const uint32_t* a,
                                         uint32_t b0, uint32_t b1) {
    asm volatile("mma.sync.aligned.m16n8k16.row.col.f32.f16.f16.f32 "
                 "{%0,%1,%2,%3}, {%4,%5,%6,%7}, {%8,%9}, {%0,%1,%2,%3};"
                 : "+f"(c[0]), "+f"(c[1]), "+f"(c[2]), "+f"(c[3])
                 : "r"(a[0]), "r"(a[1]), "r"(a[2]), "r"(a[3]), "r"(b0), "r"(b1));
}

// ================= main kernel: M=64 tiles, grid 1480 = exactly 2 waves =================
// CTAs 0..87 process a second tile (tile_id + 1480) -> no 88-CTA third wave.
#define X_OFF   0
#define Z_OFF   12800
#define B_OFF   12928
#define B_BUF   8192
#define SMEM_SZ 29312
#define NT      128
#define NTILES  1568
#define GRID1   1480

__global__ __launch_bounds__(NT, 5)
void rconv_mma_kernel(const int* __restrict__ mask, float* __restrict__ out)
{
    extern __shared__ __align__(128) char smem[];
    const uint32_t sb = smem_u32(smem);

    const int tid  = threadIdx.x;
    const int wid  = tid >> 5;
    const int lane = tid & 31;

    const int wm = wid & 1;
    const int wn = wid >> 1;
    const int m0 = wm * 32;
    const int n0 = wn * 32;

    // tile-independent ldmatrix geometry
    const int ch      = lane >> 4;
    const int lanerow = lane & 15;
    const int nlocal  = (lane & 7) + ((lane >> 4) << 3);
    const int khalf   = (lane >> 3) & 1;
    int boff[2], bsw[2];
    #pragma unroll
    for (int ntp = 0; ntp < 2; ntp++) {
        int orow = n0 + ntp * 16 + nlocal;
        boff[ntp] = orow * 128;
        bsw[ntp]  = orow & 7;
    }
    const uint32_t zaddr = sb + Z_OFF;

    #pragma unroll 1
    for (int tile_id = blockIdx.x; tile_id < NTILES; tile_id += GRID1) {
        __syncthreads();   // fence prior tile's sC reads vs this tile's staging

        const int b  = tile_id / 196;
        const int tl = tile_id - b * 196;
        const int x0 = (tl % 14) * 8;
        const int y0 = (tl / 14) * 8;

        // re-zero the zero-row (epilogue sC overlaps it)
        if (tid < 32) ((float*)(smem + Z_OFF))[tid] = 0.0f;

        int  rb[2], mk[2];
        #pragma unroll
        for (int mi = 0; mi < 2; mi++) {
            int p  = m0 + mi * 16 + lanerow;
            int py = p >> 3, px = p & 7;
            rb[mi] = py * 10 + px;
            mk[mi] = __ldg(&mask[(y0 + py) * WW + (x0 + px)]);
        }

        // ---- stage x tile (10x10 rows) + B[0] ----
        for (int i = tid; i < 800; i += NT) {
            int r  = i >> 3;
            int j  = i & 7;
            int iy = r / 10, ix = r - iy * 10;
            int gy = y0 - 1 + iy, gx = x0 - 1 + ix;
            bool ok = (gy >= 0 && gy < HH && gx >= 0 && gx < WW);
            const __half* src = g_x_h +
                (ok ? (((size_t)((b * HH + gy) * WW + gx)) * CIN + j * 8) : 0);
            uint32_t dst = sb + X_OFF + r * 128 + ((j ^ (r & 7)) << 4);
            cp16(dst, src, ok ? 16u : 0u);
        }
        #pragma unroll
        for (int k = 0; k < 4; k++) {
            int i = k * NT + tid;
            int o = i >> 3, j = i & 7;
            const __half* src = g_w_h + ((0 * COUT + o) * CIN + j * 8);
            uint32_t dst = sb + B_OFF + o * 128 + ((j ^ (o & 7)) << 4);
            cp16(dst, src, 16u);
        }
        CP_COMMIT();

        float C[2][4][4];
        #pragma unroll
        for (int mi = 0; mi < 2; mi++)
            #pragma unroll
            for (int nt = 0; nt < 4; nt++)
                #pragma unroll
                for (int k = 0; k < 4; k++) C[mi][nt][k] = 0.0f;

        int buf = 0;
        #pragma unroll 1
        for (int t = 0; t < 9; t++) {
            CP_WAIT0();
            __syncthreads();

            if (t < 8) {   // prefetch B[t+1] (overlaps compute)
                #pragma unroll
                for (int k = 0; k < 4; k++) {
                    int i = k * NT + tid;
                    int o = i >> 3, j = i & 7;
                    const __half* src = g_w_h + (((t + 1) * COUT + o) * CIN + j * 8);
                    uint32_t dst = sb + B_OFF + (buf ^ 1) * B_BUF + o * 128 + ((j ^ (o & 7)) << 4);
                    cp16(dst, src, 16u);
                }
                CP_COMMIT();
            }

            const int kh   = t / 3;
            const int toff = t + kh * 7;     // kh*10 + kw
            int  r128[2], rm[2];
            bool msk[2];
            #pragma unroll
            for (int mi = 0; mi < 2; mi++) {
                int r = rb[mi] + toff;
                r128[mi] = r << 7;
                rm[mi]   = r & 7;
                msk[mi]  = (mk[mi] == t);
            }
            const uint32_t bb = sb + B_OFF + buf * B_BUF;

            #pragma unroll
            for (int kc = 0; kc < 4; kc++) {
                uint32_t A[2][4], Bv[2][4];
                #pragma unroll
                for (int mi = 0; mi < 2; mi++) {
                    uint32_t sw = (uint32_t)((((kc << 1) | ch) ^ rm[mi]) << 4);
                    uint32_t ah = msk[mi] ? zaddr : (sb + X_OFF + r128[mi] + sw);
                    ldmx4(A[mi], ah);
                }
                #pragma unroll
                for (int ntp = 0; ntp < 2; ntp++) {
                    uint32_t sw = (uint32_t)((((kc << 1) | khalf) ^ bsw[ntp]) << 4);
                    ldmx4(Bv[ntp], bb + boff[ntp] + sw);
                }
                #pragma unroll
                for (int mi = 0; mi < 2; mi++)
                    #pragma unroll
                    for (int ntp = 0; ntp < 2; ntp++)
                        #pragma unroll
                        for (int s = 0; s < 2; s++)
                            mma16816(C[mi][ntp * 2 + s], A[mi],
                                     Bv[ntp][2 * s], Bv[ntp][2 * s + 1]);
            }
            buf ^= 1;
        }

        // ---- epilogue: C -> smem [m][o] (stride 66), then float4 stores ----
        __syncthreads();
        float* sC = (float*)smem;
        const int g   = lane >> 2;
        const int tg2 = (lane & 3) * 2;
        #pragma unroll
        for (int mi = 0; mi < 2; mi++)
            #pragma unroll
            for (int nt = 0; nt < 4; nt++) {
                int mrow = m0 + mi * 16 + g;
                int col  = n0 + nt * 8 + tg2;
                *(float2*)(sC + mrow * 66 + col)       = make_float2(C[mi][nt][0], C[mi][nt][1]);
                *(float2*)(sC + (mrow + 8) * 66 + col) = make_float2(C[mi][nt][2], C[mi][nt][3]);
            }
        __syncthreads();

        #pragma unroll
        for (int it = 0; it < 8; it++) {
            int idx = it * NT + tid;
            int o   = idx >> 4;
            int rem = idx & 15;
            int py  = rem >> 1;
            int px  = (rem & 1) * 4;
            int mb  = py * 8 + px;
            float4 v;
            v.x = sC[(mb + 0) * 66 + o];
            v.y = sC[(mb + 1) * 66 + o];
            v.z = sC[(mb + 2) * 66 + o];
            v.w = sC[(mb + 3) * 66 + o];
            *(float4*)(out + ((size_t)(b * COUT + o)) * HWSZ + (y0 + py) * WW + (x0 + px)) = v;
        }
    }
}

// ================= launch: single stream, prep-all then main-all =================
extern "C" void kernel_launch(void* const* d_in, const int* in_sizes, int n_in,
                              void* d_out, int out_size)
{
    (void)in_sizes; (void)n_in; (void)out_size;
    const float* x    = (const float*)d_in[0];
    const float* w    = (const float*)d_in[1];
    const int*   mask = (const int*)d_in[2];
    float*       out  = (float*)d_out;

    prep_kernel<<<dim3(232, BATCH), 128>>>(x, w);

    cudaFuncSetAttribute(rconv_mma_kernel,
                         cudaFuncAttributeMaxDynamicSharedMemorySize, SMEM_SZ);
    rconv_mma_kernel<<<GRID1, NT, SMEM_SZ>>>(mask, out);
}

// round 17
// speedup vs baseline: 1.6412x; 1.0062x over previous
#include <cuda_runtime.h>
#include <cuda_fp16.h>
#include <cstdint>

#define BATCH 8
#define CIN   64
#define COUT  64
#define HH    112
#define WW    112
#define HWSZ  (HH*WW)

// ---------------- precomputed fp16 planes ----------------
__device__ __align__(128) __half g_x_h[BATCH * HH * WW * CIN];   // [b][y][x][c]
__device__ __align__(128) __half g_w_h[9 * COUT * CIN];          // [t][o][c]

// ================= fused prep (known-good since R12) =================
#define PS 114

__global__ __launch_bounds__(128, 15)
void prep_kernel(const float* __restrict__ x, const float* __restrict__ w)
{
    __shared__ __align__(16) __half stile[CIN * PS];
    const int tid = threadIdx.x;
    const int bx  = blockIdx.x;
    const int b   = blockIdx.y;

    if (bx >= 224) {
        const int slot = (bx - 224) + 8 * b;      // 0..63
        #pragma unroll
        for (int j = 0; j < 5; j++) {
            int el = j * 128 + tid;
            if (el < 576) {
                int e = slot * 576 + el;
                int c = e & 63, o = (e >> 6) & 63, t = e >> 12;
                g_w_h[(t * COUT + o) * CIN + c] =
                    __float2half(w[o * (CIN * 9) + c * 9 + t]);
            }
        }
        return;
    }

    const int y    = bx >> 1;
    const int half = (bx & 1) * 56;
    const float* xb = x + ((size_t)b * CIN) * HWSZ + y * WW + half;

    #pragma unroll
    for (int k = 0; k < 8; k++) {
        int u   = k * 128 + tid;
        int c   = u >> 4;
        int sub = u & 15;
        if (sub < 14) {
            float4 v = *(const float4*)&xb[(size_t)c * HWSZ + sub * 4];
            __half2 h0 = __floats2half2_rn(v.x, v.y);
            __half2 h1 = __floats2half2_rn(v.z, v.w);
            *(__half2*)&stile[c * PS + sub * 4]     = h0;
            *(__half2*)&stile[c * PS + sub * 4 + 2] = h1;
        }
    }
    __syncthreads();

    const int cg = tid & 7;
    #pragma unroll
    for (int j = 0; j < 4; j++) {
        int xx = j * 16 + (tid >> 3);
        if (xx < 56) {
            __half h[8];
            #pragma unroll
            for (int k = 0; k < 8; k++)
                h[k] = stile[(cg * 8 + k) * PS + xx];
            *(uint4*)&g_x_h[((size_t)((b * HH + y) * WW) + half + xx) * CIN + cg * 8] =
                *(uint4*)h;
        }
    }
}

// ================= base-ISA async/MMA primitives =================
__device__ __forceinline__ uint32_t smem_u32(const void* p) {
    uint32_t a;
    asm("{ .reg .u64 t; cvta.to.shared.u64 t, %1; cvt.u32.u64 %0, t; }" : "=r"(a) : "l"(p));
    return a;
}
__device__ __forceinline__ void cp16(uint32_t dst, const void* src, uint32_t sz) {
    asm volatile("cp.async.cg.shared.global [%0], [%1], 16, %2;"
                 :: "r"(dst), "l"(src), "r"(sz) : "memory");
}
#define CP_COMMIT() asm volatile("cp.async.commit_group;" ::: "memory")
#define CP_WAIT0()  asm volatile("cp.async.wait_group 0;" ::: "memory")
#define CP_WAIT1()  asm volatile("cp.async.wait_group 1;" ::: "memory")

__device__ __forceinline__ void ldmx4(uint32_t* r, uint32_t addr) {
    asm volatile("ldmatrix.sync.aligned.m8n8.x4.shared.b16 {%0,%1,%2,%3}, [%4];"
                 : "=r"(r[0]), "=r"(r[1]), "=r"(r[2]), "=r"(r[3]) : "r"(addr));
}
__device__ __forceinline__ void mma16816(float* c, const uint32_t* a,
                                         uint32_t b0, uint32_t b1) {
    asm volatile("mma.sync.aligned.m16n8k16.row.col.f32.f16.f16.f32 "
                 "{%0,%1,%2,%3}, {%4,%5,%6,%7}, {%8,%9}, {%0,%1,%2,%3};"
                 : "+f"(c[0]), "+f"(c[1]), "+f"(c[2]), "+f"(c[3])
                 : "r"(a[0]), "r"(a[1]), "r"(a[2]), "r"(a[3]), "r"(b0), "r"(b1));
}

// ================= main kernel: barrier-free tap loop (warp-private B) =================
// smem: [0, 12800)   x tile: 100 rows (10x10) x 128B, XOR-swizzled, read-only after prologue
//       [12800, 12928) zero row
//       [12928, 45696) B: 4 warps x 2 bufs x 4KB (warp-private double buffer)
// epilogue reuses [0, 16896) as C[64][66] fp32.
#define X_OFF    0
#define Z_OFF    12800
#define B_OFF    12928
#define WB_SZ    8192     // per-warp region (2 x 4KB)
#define B_BUF    4096
#define SMEM_SZ  45696
#define NT       128

__global__ __launch_bounds__(NT, 4)
void rconv_mma_kernel(const int* __restrict__ mask, float* __restrict__ out)
{
    extern __shared__ __align__(128) char smem[];
    const uint32_t sb = smem_u32(smem);

    const int tid  = threadIdx.x;
    const int wid  = tid >> 5;
    const int lane = tid & 31;
    const int tile = blockIdx.x;            // 0..195
    const int b    = blockIdx.y;
    const int x0   = (tile % 14) * 8;
    const int y0   = (tile / 14) * 8;

    const int wm = wid & 1;
    const int wn = wid >> 1;
    const int m0 = wm * 32;
    const int n0 = wn * 32;                 // this warp's output-channel base

    if (tid < 32) ((float*)(smem + Z_OFF))[tid] = 0.0f;

    // ---- per-thread ldmatrix geometry ----
    const int ch      = lane >> 4;
    const int lanerow = lane & 15;
    int  rb[2], mk[2];
    #pragma unroll
    for (int mi = 0; mi < 2; mi++) {
        int p  = m0 + mi * 16 + lanerow;
        int py = p >> 3, px = p & 7;
        rb[mi] = py * 10 + px;
        mk[mi] = __ldg(&mask[(y0 + py) * WW + (x0 + px)]);
    }
    const int nlocal = (lane & 7) + ((lane >> 4) << 3);
    const int khalf  = (lane >> 3) & 1;
    int boff[2], bsw[2];                    // LOCAL row offsets in warp buffer
    #pragma unroll
    for (int ntp = 0; ntp < 2; ntp++) {
        int rloc = ntp * 16 + nlocal;       // 0..31
        boff[ntp] = rloc * 128;
        bsw[ntp]  = rloc & 7;
    }
    const uint32_t zaddr = sb + Z_OFF;
    const uint32_t wbase = sb + B_OFF + wid * WB_SZ;

    // per-lane B staging geometry: 8 cp16/lane/tap, lanes 0-7 = one 128B row
    const int st_j = lane & 7;
    const int st_r = lane >> 3;             // 0..3, +4 per iter

    // ---- prologue: stage x tile (CTA-wide) + own-warp B[0]; ONE barrier ----
    for (int i = tid; i < 800; i += NT) {
        int r  = i >> 3;
        int j  = i & 7;
        int iy = r / 10, ix = r - iy * 10;
        int gy = y0 - 1 + iy, gx = x0 - 1 + ix;
        bool ok = (gy >= 0 && gy < HH && gx >= 0 && gx < WW);
        const __half* src = g_x_h +
            (ok ? (((size_t)((b * HH + gy) * WW + gx)) * CIN + j * 8) : 0);
        uint32_t dst = sb + X_OFF + r * 128 + ((j ^ (r & 7)) << 4);
        cp16(dst, src, ok ? 16u : 0u);
    }
    #pragma unroll
    for (int k = 0; k < 8; k++) {           // B[0] -> warp buf 0
        int rloc = st_r + k * 4;            // 0..31
        const __half* src = g_w_h + ((0 * COUT + n0 + rloc) * CIN + st_j * 8);
        uint32_t dst = wbase + rloc * 128 + ((st_j ^ (rloc & 7)) << 4);
        cp16(dst, src, 16u);
    }
    CP_COMMIT();
    CP_WAIT0();
    __syncthreads();                         // x tile visible CTA-wide; B0 visible in-warp

    float C[2][4][4];
    #pragma unroll
    for (int mi = 0; mi < 2; mi++)
        #pragma unroll
        for (int nt = 0; nt < 4; nt++)
            #pragma unroll
            for (int k = 0; k < 4; k++) C[mi][nt][k] = 0.0f;

    // ---- tap loop: NO CTA barriers ----
    #pragma unroll 1
    for (int t = 0; t < 9; t++) {
        // prefetch own-warp B[t+1] into the other buffer (reads of that buffer
        // were LDSMs issued last iteration — cutlass-style cp.async reuse)
        if (t < 8) {
            const uint32_t pb = wbase + ((t + 1) & 1) * B_BUF;
            #pragma unroll
            for (int k = 0; k < 8; k++) {
                int rloc = st_r + k * 4;
                const __half* src = g_w_h + (((t + 1) * COUT + n0 + rloc) * CIN + st_j * 8);
                cp16(pb + rloc * 128 + ((st_j ^ (rloc & 7)) << 4), src, 16u);
            }
            CP_COMMIT();
            CP_WAIT1();                      // <=1 outstanding -> B[t] done
        } else {
            CP_WAIT0();
        }
        __syncwarp();

        const int kh   = t / 3;
        const int toff = t + kh * 7;         // kh*10 + kw
        int  r128[2], rm[2];
        bool msk[2];
        #pragma unroll
        for (int mi = 0; mi < 2; mi++) {
            int r = rb[mi] + toff;
            r128[mi] = r << 7;
            rm[mi]   = r & 7;
            msk[mi]  = (mk[mi] == t);
        }
        const uint32_t bb = wbase + (t & 1) * B_BUF;

        #pragma unroll
        for (int kc = 0; kc < 4; kc++) {
            uint32_t A[2][4], Bv[2][4];
            #pragma unroll
            for (int mi = 0; mi < 2; mi++) {
                uint32_t sw = (uint32_t)((((kc << 1) | ch) ^ rm[mi]) << 4);
                uint32_t ah = msk[mi] ? zaddr : (sb + X_OFF + r128[mi] + sw);
                ldmx4(A[mi], ah);
            }
            #pragma unroll
            for (int ntp = 0; ntp < 2; ntp++) {
                uint32_t sw = (uint32_t)((((kc << 1) | khalf) ^ bsw[ntp]) << 4);
                ldmx4(Bv[ntp], bb + boff[ntp] + sw);
            }
            #pragma unroll
            for (int mi = 0; mi < 2; mi++)
                #pragma unroll
                for (int ntp = 0; ntp < 2; ntp++)
                    #pragma unroll
                    for (int s = 0; s < 2; s++)
                        mma16816(C[mi][ntp * 2 + s], A[mi],
                                 Bv[ntp][2 * s], Bv[ntp][2 * s + 1]);
        }
    }

    // ---- epilogue: C -> smem [m][o] (stride 66), then float4 stores ----
    __syncthreads();
    float* sC = (float*)smem;
    const int g   = lane >> 2;
    const int tg2 = (lane & 3) * 2;
    #pragma unroll
    for (int mi = 0; mi < 2; mi++)
        #pragma unroll
        for (int nt = 0; nt < 4; nt++) {
            int mrow = m0 + mi * 16 + g;
            int col  = n0 + nt * 8 + tg2;
            *(float2*)(sC + mrow * 66 + col)       = make_float2(C[mi][nt][0], C[mi][nt][1]);
            *(float2*)(sC + (mrow + 8) * 66 + col) = make_float2(C[mi][nt][2], C[mi][nt][3]);
        }
    __syncthreads();

    #pragma unroll
    for (int it = 0; it < 8; it++) {
        int idx = it * NT + tid;
        int o   = idx >> 4;
        int rem = idx & 15;
        int py  = rem >> 1;
        int px  = (rem & 1) * 4;
        int mb  = py * 8 + px;
        float4 v;
        v.x = sC[(mb + 0) * 66 + o];
        v.y = sC[(mb + 1) * 66 + o];
        v.z = sC[(mb + 2) * 66 + o];
        v.w = sC[(mb + 3) * 66 + o];
        *(float4*)(out + ((size_t)(b * COUT + o)) * HWSZ + (y0 + py) * WW + (x0 + px)) = v;
    }
}

// ================= launch =================
extern "C" void kernel_launch(void* const* d_in, const int* in_sizes, int n_in,
                              void* d_out, int out_size)
{
    (void)in_sizes; (void)n_in; (void)out_size;
    const float* x    = (const float*)d_in[0];
    const float* w    = (const float*)d_in[1];
    const int*   mask = (const int*)d_in[2];
    float*       out  = (float*)d_out;

    prep_kernel<<<dim3(232, BATCH), 128>>>(x, w);

    cudaFuncSetAttribute(rconv_mma_kernel,
                         cudaFuncAttributeMaxDynamicSharedMemorySize, SMEM_SZ);
    rconv_mma_kernel<<<dim3(196, BATCH), NT, SMEM_SZ>>>(mask, out);
}